// round 16
// baseline (speedup 1.0000x reference)
#include <cuda_runtime.h>
#include <cstdint>

#define NSTEP 128
#define BATCH 8192
#define BC    64
#define NT    128
#define HLD   132            // hcat row stride (words); 132 % 32 == 4 -> conflict-free ldm
#define W0LD  68             // W_hh0 row stride (words); 68 % 32 == 4
#define W1LD  132            // [W_ih1|W_hh1] row stride (words)
#define HBUF  (BC*HLD)

// ---- SMEM word offsets ----
#define HCAT_OFF  0                           // 2 x 64 x 132 words
#define W0_OFF    (2*HBUF)                    // 128 x 68 words
#define W1_OFF    (W0_OFF + 128*W0LD)         // 128 x 132 words
#define SCTAB_OFF (W1_OFF + 128*W1LD)         // 3*128 floats
#define SB1V_OFF  (SCTAB_OFF + 384)           // 128 floats
#define SWD_OFF   (SB1V_OFF + 128)            // 2*128 floats
#define SMEM_WORDS (SWD_OFF + 256)
#define SMEM_BYTES (SMEM_WORDS * 4)           // ~173KB -> 1 CTA/SM

__device__ __forceinline__ uint32_t pk_bf(float even, float odd) {
    uint32_t r; asm("cvt.rn.bf16x2.f32 %0, %1, %2;" : "=r"(r) : "f"(odd), "f"(even));
    return r;
}
__device__ __forceinline__ float tanh_fast(float x) {
    float y; asm("tanh.approx.f32 %0, %1;" : "=f"(y) : "f"(x)); return y;
}
__device__ __forceinline__ uint32_t smem_u32(const void* p) {
    uint32_t a;
    asm("{ .reg .u64 t; cvta.to.shared.u64 t, %1; cvt.u32.u64 %0, t; }" : "=r"(a) : "l"(p));
    return a;
}
__device__ __forceinline__ void ldm4(uint32_t* a, uint32_t addr) {
    asm volatile("ldmatrix.sync.aligned.m8n8.x4.shared.b16 {%0,%1,%2,%3}, [%4];"
                 : "=r"(a[0]), "=r"(a[1]), "=r"(a[2]), "=r"(a[3]) : "r"(addr));
}
__device__ __forceinline__ void mma16(float* d, const uint32_t* a, const uint32_t* b) {
    asm volatile("mma.sync.aligned.m16n8k16.row.col.f32.bf16.bf16.f32 "
                 "{%0,%1,%2,%3}, {%4,%5,%6,%7}, {%8,%9}, {%0,%1,%2,%3};"
                 : "+f"(d[0]), "+f"(d[1]), "+f"(d[2]), "+f"(d[3])
                 : "r"(a[0]), "r"(a[1]), "r"(a[2]), "r"(a[3]), "r"(b[0]), "r"(b[1]));
}

__global__ void __launch_bounds__(NT, 1)
rnn_priv_kernel(const float* __restrict__ samples,
                const float* __restrict__ W_ih0, const float* __restrict__ b_ih0,
                const float* __restrict__ W_hh0, const float* __restrict__ b_hh0,
                const float* __restrict__ W_ih1, const float* __restrict__ b_ih1,
                const float* __restrict__ W_hh1, const float* __restrict__ b_hh1,
                const float* __restrict__ W_dense, const float* __restrict__ b_dense,
                float* __restrict__ out)
{
    extern __shared__ float smf[];
    uint32_t* hcat  = (uint32_t*)(smf + HCAT_OFF);
    uint32_t* sW0   = (uint32_t*)(smf + W0_OFF);
    uint32_t* sW1   = (uint32_t*)(smf + W1_OFF);
    float*    scTab = smf + SCTAB_OFF;
    float*    sB1v  = smf + SB1V_OFF;
    float*    sWd   = smf + SWD_OFF;

    const int tid = threadIdx.x;
    const int w   = tid >> 5;          // warp owns rows [w*16, w*16+16)
    const int lane = tid & 31;
    const int g  = lane >> 2;
    const int tq = lane & 3;

    // ---- one-time init (weights -> bf16 SMEM, tables) ----
    for (int idx = tid; idx < 128 * 64; idx += NT) {
        const int j = idx >> 6, kw = idx & 63;
        sW0[j * W0LD + kw]      = pk_bf(W_hh0[j * 128 + 2 * kw], W_hh0[j * 128 + 2 * kw + 1]);
        sW1[j * W1LD + kw]      = pk_bf(W_ih1[j * 128 + 2 * kw], W_ih1[j * 128 + 2 * kw + 1]);
        sW1[j * W1LD + 64 + kw] = pk_bf(W_hh1[j * 128 + 2 * kw], W_hh1[j * 128 + 2 * kw + 1]);
    }
    if (tid < 128) {
        const int j = tid;
        float bb = b_ih0[j] + b_hh0[j];
        scTab[j]       = bb + W_ih0[2 * j];
        scTab[128 + j] = bb + W_ih0[2 * j + 1];
        scTab[256 + j] = bb;
        sB1v[j] = b_ih1[j] + b_hh1[j];
        sWd[j]       = W_dense[j];
        sWd[128 + j] = W_dense[128 + j];
    }
    for (int idx = tid; idx < HBUF; idx += NT) hcat[idx] = 0u;   // buffer 0 zeroed
    __syncthreads();   // the ONLY CTA-wide barrier in the kernel

    // ldmatrix A base: this warp's 16 rows (buffer 0, byte address)
    const uint32_t hbA = smem_u32(hcat)
        + (uint32_t)((w * 16 + (lane & 7) + ((lane >> 3) & 1) * 8) * HLD) * 4u
        + (uint32_t)(((lane >> 4) & 1) * 16);
    // ldmatrix B lane bases (n-pair tiling, validated pattern)
    const int brow = ((lane >> 4) & 1) * 8 + (lane & 7);
    const int bh4  = ((lane >> 3) & 1) * 4;
    const uint32_t bW0 = smem_u32(sW0) + (uint32_t)(brow * W0LD + bh4) * 4u;
    const uint32_t bW1 = smem_u32(sW1) + (uint32_t)(brow * W1LD + bh4) * 4u;

    const float bd0 = b_dense[0], bd1 = b_dense[1];
    const int rowg = blockIdx.x * BC + w * 16 + g;   // global batch row for (hh=0)
    int bitA = 2, bitB = 2;                          // prev sampled bit rows g, g+8
    float lp0 = 0.f, lp1 = 0.f;

    for (int t = 0; t < NSTEP; ++t) {
        const uint32_t rdoff = (uint32_t)(t & 1) * (HBUF * 4);
        const uint32_t wroff = (uint32_t)((t & 1) ^ 1) * (HBUF * 4);
        uint32_t* hcwm = hcat + ((t & 1) ^ 1) * HBUF;

        const float s1a = __ldg(&samples[(t * BATCH + rowg) * 2 + 1]);
        const float s1b = __ldg(&samples[(t * BATCH + rowg + 8) * 2 + 1]);

        // ========== L0: acc0 = h0[rd] @ W_hh0^T (16 rows x 128 cols) ==========
        float acc0[16][4];
#pragma unroll
        for (int nt = 0; nt < 16; ++nt)
#pragma unroll
            for (int i = 0; i < 4; ++i) acc0[nt][i] = 0.f;

#pragma unroll
        for (int kt = 0; kt < 8; ++kt) {
            uint32_t a[4];
            ldm4(a, hbA + rdoff + (uint32_t)(kt * 32));
#pragma unroll
            for (int p = 0; p < 8; ++p) {
                uint32_t b[4];
                ldm4(b, bW0 + (uint32_t)(p * 16 * W0LD * 4 + kt * 32));
                mma16(acc0[2 * p],     a, b);
                mma16(acc0[2 * p + 1], a, b + 2);
            }
        }

        // ---- epilogue0: h0' = tanh(acc0 + bias + onehot(bit)) -> h0[wr] ----
#pragma unroll
        for (int hh = 0; hh < 2; ++hh) {
            const int bit = hh ? bitB : bitA;
            const float* cs = scTab + bit * 128;
            const int row = w * 16 + g + hh * 8;
#pragma unroll
            for (int nt = 0; nt < 16; ++nt) {
                const int jc = nt * 8 + 2 * tq;
                const float2 c2 = *(const float2*)(cs + jc);
                float v0 = acc0[nt][hh * 2]     + c2.x;
                float v1 = acc0[nt][hh * 2 + 1] + c2.y;
                hcwm[row * HLD + nt * 4 + tq] = pk_bf(tanh_fast(v0), tanh_fast(v1));
            }
        }
        __syncwarp();   // cross-lane RAW: epi0 STS -> L1 ldmatrix (warp-local)

        // ========== L1: acc1 = [h0'[wr] | h1[rd]] @ [W_ih1|W_hh1]^T (K=256) ====
        float acc1[16][4];
#pragma unroll
        for (int nt = 0; nt < 16; ++nt)
#pragma unroll
            for (int i = 0; i < 4; ++i) acc1[nt][i] = 0.f;

#pragma unroll
        for (int kt = 0; kt < 16; ++kt) {
            uint32_t a[4];
            const uint32_t aaddr = (kt < 8)
                ? (hbA + wroff + (uint32_t)(kt * 32))
                : (hbA + rdoff + 256u + (uint32_t)((kt - 8) * 32));
            ldm4(a, aaddr);
#pragma unroll
            for (int p = 0; p < 8; ++p) {
                uint32_t b[4];
                ldm4(b, bW1 + (uint32_t)(p * 16 * W1LD * 4 + kt * 32));
                mma16(acc1[2 * p],     a, b);
                mma16(acc1[2 * p + 1], a, b + 2);
            }
        }

        // ---- epilogue1: h1' = tanh(acc1 + b1) -> h1[wr]; dense in registers ----
        float q00 = 0.f, q01 = 0.f, q10 = 0.f, q11 = 0.f;   // [hh][logit]
#pragma unroll
        for (int hh = 0; hh < 2; ++hh) {
            const int row = w * 16 + g + hh * 8;
#pragma unroll
            for (int nt = 0; nt < 16; ++nt) {
                const int jc = nt * 8 + 2 * tq;
                const float2 b2 = *(const float2*)(sB1v + jc);
                float v0 = acc1[nt][hh * 2]     + b2.x;
                float v1 = acc1[nt][hh * 2 + 1] + b2.y;
                float t0 = tanh_fast(v0), t1 = tanh_fast(v1);
                const float2 w0d = *(const float2*)(sWd + jc);
                const float2 w1d = *(const float2*)(sWd + 128 + jc);
                if (hh == 0) {
                    q00 = fmaf(t0, w0d.x, fmaf(t1, w0d.y, q00));
                    q01 = fmaf(t0, w1d.x, fmaf(t1, w1d.y, q01));
                } else {
                    q10 = fmaf(t0, w0d.x, fmaf(t1, w0d.y, q10));
                    q11 = fmaf(t0, w1d.x, fmaf(t1, w1d.y, q11));
                }
                hcwm[row * HLD + 64 + nt * 4 + tq] = pk_bf(t0, t1);
            }
        }
        // xor-shfl over tq-subgroup: symmetric -> all 4 lanes get full sums
        q00 += __shfl_xor_sync(0xffffffffu, q00, 1);
        q00 += __shfl_xor_sync(0xffffffffu, q00, 2);
        q01 += __shfl_xor_sync(0xffffffffu, q01, 1);
        q01 += __shfl_xor_sync(0xffffffffu, q01, 2);
        q10 += __shfl_xor_sync(0xffffffffu, q10, 1);
        q10 += __shfl_xor_sync(0xffffffffu, q10, 2);
        q11 += __shfl_xor_sync(0xffffffffu, q11, 1);
        q11 += __shfl_xor_sync(0xffffffffu, q11, 2);

        {   // row g
            float L0 = q00 + bd0, L1 = q01 + bd1;
            float m = fmaxf(L0, L1);
            float lse = m + __logf(__expf(L0 - m) + __expf(L1 - m));
            int bit = (s1a > 0.5f) ? 1 : 0;
            lp0 += (bit ? L1 : L0) - lse;
            bitA = bit;
        }
        {   // row g+8
            float L0 = q10 + bd0, L1 = q11 + bd1;
            float m = fmaxf(L0, L1);
            float lse = m + __logf(__expf(L0 - m) + __expf(L1 - m));
            int bit = (s1b > 0.5f) ? 1 : 0;
            lp1 += (bit ? L1 : L0) - lse;
            bitB = bit;
        }
        // no barrier: next step's L0 reads [wr] written by this warp only;
        // __syncwarp at top of next epi0->L1 boundary orders remaining hazards
    }

    if (tq == 0) out[rowg]     = lp0;
    if (tq == 1) out[rowg + 8] = lp1;
}

extern "C" void kernel_launch(void* const* d_in, const int* in_sizes, int n_in,
                              void* d_out, int out_size) {
    (void)in_sizes; (void)n_in; (void)out_size;
    cudaFuncSetAttribute(rnn_priv_kernel,
                         cudaFuncAttributeMaxDynamicSharedMemorySize, SMEM_BYTES);
    rnn_priv_kernel<<<BATCH / BC, NT, SMEM_BYTES>>>(
        (const float*)d_in[0],
        (const float*)d_in[1], (const float*)d_in[2],
        (const float*)d_in[3], (const float*)d_in[4],
        (const float*)d_in[5], (const float*)d_in[6],
        (const float*)d_in[7], (const float*)d_in[8],
        (const float*)d_in[9], (const float*)d_in[10],
        (float*)d_out);
}

// round 17
// speedup vs baseline: 2.2281x; 2.2281x over previous
#include <cuda_runtime.h>
#include <cstdint>

#define NSTEP 128
#define BATCH 8192
#define BC    32
#define NT    128
#define HLD   132            // hcat row stride in 32-bit words (bf16x2), conflict-free
#define WLD   132            // wB1 row stride in words
#define HBUF  (BC*HLD)       // one hcat buffer, words

// ---- SMEM byte offsets ----
#define HCAT_OFF  0                          // 2 buffers x 32 rows x HLD words: [h0|h1|pad]
#define WB1_OFF   (HCAT_OFF + 2*HBUF*4)      // 128 rows x WLD words: [W_ih1(64w) | W_hh1(64w)]
#define SCTAB_OFF (WB1_OFF + 128*WLD*4)      // 3*128 floats (layer0 bias + one-hot select)
#define SB1V_OFF  (SCTAB_OFF + 1536)         // 128 floats
#define SWD_OFF   (SB1V_OFF + 512)           // 2*128 floats
#define SBIT_OFF  (SWD_OFF + 1024)           // 32 ints
#define SPART_OFF (SBIT_OFF + 128)           // 4 warps x 2 x 32 floats
#define SMEM_BYTES (SPART_OFF + 4*64*4)      // ~107KB -> 2 CTAs/SM

__device__ __forceinline__ uint32_t pk_bf(float even, float odd) {
    uint32_t r; asm("cvt.rn.bf16x2.f32 %0, %1, %2;" : "=r"(r) : "f"(odd), "f"(even));
    return r;
}
__device__ __forceinline__ float tanh_fast(float x) {
    float y; asm("tanh.approx.f32 %0, %1;" : "=f"(y) : "f"(x)); return y;
}
__device__ __forceinline__ uint32_t smem_u32(const void* p) {
    uint32_t a;
    asm("{ .reg .u64 t; cvta.to.shared.u64 t, %1; cvt.u32.u64 %0, t; }" : "=r"(a) : "l"(p));
    return a;
}
__device__ __forceinline__ void ldmA(uint32_t* a, uint32_t addr) {
    asm volatile("ldmatrix.sync.aligned.m8n8.x4.shared.b16 {%0,%1,%2,%3}, [%4];"
                 : "=r"(a[0]), "=r"(a[1]), "=r"(a[2]), "=r"(a[3]) : "r"(addr));
}
__device__ __forceinline__ void mma16(float* d, const uint32_t* a, const uint32_t* b) {
    asm volatile("mma.sync.aligned.m16n8k16.row.col.f32.bf16.bf16.f32 "
                 "{%0,%1,%2,%3}, {%4,%5,%6,%7}, {%8,%9}, {%0,%1,%2,%3};"
                 : "+f"(d[0]), "+f"(d[1]), "+f"(d[2]), "+f"(d[3])
                 : "r"(a[0]), "r"(a[1]), "r"(a[2]), "r"(a[3]), "r"(b[0]), "r"(b[1]));
}
#define BAR_SYNC(id)   asm volatile("bar.sync %0, %1;"   :: "n"(id), "n"(NT) : "memory")
#define BAR_ARRIVE(id) asm volatile("bar.arrive %0, %1;" :: "n"(id), "n"(NT) : "memory")

__global__ void __launch_bounds__(NT, 2)
rnn_bf16k_kernel(const float* __restrict__ samples,
                 const float* __restrict__ W_ih0, const float* __restrict__ b_ih0,
                 const float* __restrict__ W_hh0, const float* __restrict__ b_hh0,
                 const float* __restrict__ W_ih1, const float* __restrict__ b_ih1,
                 const float* __restrict__ W_hh1, const float* __restrict__ b_hh1,
                 const float* __restrict__ W_dense, const float* __restrict__ b_dense,
                 float* __restrict__ out)
{
    extern __shared__ char smem[];
    uint32_t* hcat  = (uint32_t*)(smem + HCAT_OFF);
    uint32_t* wB1   = (uint32_t*)(smem + WB1_OFF);
    float*    scTab = (float*)(smem + SCTAB_OFF);
    float*    sB1v  = (float*)(smem + SB1V_OFF);
    float*    sWd   = (float*)(smem + SWD_OFF);
    int*      sBit  = (int*)(smem + SBIT_OFF);
    float*    sPart = (float*)(smem + SPART_OFF);

    const int tid = threadIdx.x;
    const int w   = tid >> 5;         // 0..3, owns 32 n-cols
    const int lane = tid & 31;
    const int g  = lane >> 2;
    const int tq = lane & 3;
    const int gRow = blockIdx.x * BC + tid;   // valid for tid < 32

    // ---- resident W_hh0 B-fragments (bf16): 4 n8-tiles x 8 k-tiles ----
    uint32_t w0[4][8][2];
#pragma unroll
    for (int nt = 0; nt < 4; ++nt) {
        const int j = 32 * w + nt * 8 + g;
#pragma unroll
        for (int kt = 0; kt < 8; ++kt) {
            const float* p = W_hh0 + j * 128 + kt * 16;
            w0[nt][kt][0] = pk_bf(p[2 * tq],     p[2 * tq + 1]);
            w0[nt][kt][1] = pk_bf(p[8 + 2 * tq], p[8 + 2 * tq + 1]);
        }
    }

    // ---- SMEM weight/bias tables ----
    for (int idx = tid; idx < 128 * 64; idx += NT) {
        const int j = idx >> 6, kw = idx & 63;
        wB1[j * WLD + kw]      = pk_bf(W_ih1[j * 128 + 2 * kw], W_ih1[j * 128 + 2 * kw + 1]);
        wB1[j * WLD + 64 + kw] = pk_bf(W_hh1[j * 128 + 2 * kw], W_hh1[j * 128 + 2 * kw + 1]);
    }
    if (tid < 128) {
        const int j = tid;
        float bb = b_ih0[j] + b_hh0[j];
        scTab[j]       = bb + W_ih0[2 * j];
        scTab[128 + j] = bb + W_ih0[2 * j + 1];
        scTab[256 + j] = bb;
        sB1v[j] = b_ih1[j] + b_hh1[j];
        sWd[j]       = W_dense[j];
        sWd[128 + j] = W_dense[128 + j];
    }
    for (int idx = tid; idx < HBUF; idx += NT) hcat[idx] = 0u;   // buffer 0 zeroed
    if (tid < BC) sBit[tid] = 2;
    __syncthreads();

    // ---- phase-skew: second-wave CTAs (co-resident partner is bid-148) delay
    //      ~half a step so the two CTAs' crossbar-heavy phases interleave ----
    if (blockIdx.x >= 148) {
        int p = 0;
#pragma unroll 1
        for (int i = 0; i < 80; ++i)           // 80 x ~29cyc dependent LDS ~ 2300 cyc
            p = ((volatile int*)hcat)[p & 31]; // hcat[0..31] are zero
        if (p == -12345) out[0] = 0.f;         // never taken; keeps chain ordered
    }

    // ldmatrix per-lane A address base (buffer 0)
    const uint32_t hb0 = smem_u32(hcat)
        + (uint32_t)(((lane & 7) + ((lane >> 3) & 1) * 8) * HLD) * 4u
        + (uint32_t)(((lane >> 4) & 1) * 16);
    const float bd0 = b_dense[0], bd1 = b_dense[1];
    float lp = 0.f;

    for (int t = 0; t < NSTEP; ++t) {
        const uint32_t rdoff = (uint32_t)(t & 1) * (HBUF * 4);
        const uint32_t wroff = (uint32_t)((t & 1) ^ 1) * (HBUF * 4);
        uint32_t* hcwm = hcat + ((t & 1) ^ 1) * HBUF;   // write buffer

        float s1 = 0.f;
        if (tid < BC) s1 = __ldg(&samples[(t * BATCH + gRow) * 2 + 1]);

        // ========== layer0: D = h0[rd] @ W_hh0^T (K=128) ==========
        float acc[2][4][4];
#pragma unroll
        for (int mt = 0; mt < 2; ++mt)
#pragma unroll
            for (int nt = 0; nt < 4; ++nt)
#pragma unroll
                for (int i = 0; i < 4; ++i) acc[mt][nt][i] = 0.f;

#pragma unroll
        for (int kt = 0; kt < 8; ++kt) {
#pragma unroll
            for (int mt = 0; mt < 2; ++mt) {
                uint32_t a[4];
                ldmA(a, hb0 + rdoff + (uint32_t)(mt * 16 * HLD * 4) + (uint32_t)(kt * 32));
#pragma unroll
                for (int nt = 0; nt < 4; ++nt)
                    mma16(acc[mt][nt], a, w0[nt][kt]);
            }
        }

        // join point: warp0's dense(t-1) sBit writes become visible here
        BAR_SYNC(1);

        // ---- epilogue0: h0' = tanh(D + bias + onehot) -> h0[wr] ----
#pragma unroll
        for (int mt = 0; mt < 2; ++mt)
#pragma unroll
            for (int hh = 0; hh < 2; ++hh) {
                const int row = mt * 16 + g + hh * 8;
                const int bit = sBit[row];
                const float* cs = scTab + bit * 128;
#pragma unroll
                for (int nt = 0; nt < 4; ++nt) {
                    const int jc = 32 * w + nt * 8 + 2 * tq;
                    float v0 = acc[mt][nt][hh * 2]     + cs[jc];
                    float v1 = acc[mt][nt][hh * 2 + 1] + cs[jc + 1];
                    hcwm[row * HLD + 16 * w + nt * 4 + tq] =
                        pk_bf(tanh_fast(v0), tanh_fast(v1));
                }
            }
        __syncthreads();   // h0'[wr] visible to all warps

        // ========== layer1: D = [h0'[wr] | h1[rd]] @ [W_ih1|W_hh1]^T (K=256) ==========
#pragma unroll
        for (int mt = 0; mt < 2; ++mt)
#pragma unroll
            for (int nt = 0; nt < 4; ++nt)
#pragma unroll
                for (int i = 0; i < 4; ++i) acc[mt][nt][i] = 0.f;

#pragma unroll
        for (int kt = 0; kt < 16; ++kt) {
            uint32_t b[4][2];
#pragma unroll
            for (int nt = 0; nt < 4; ++nt) {
                const uint32_t* wp = wB1 + (32 * w + nt * 8 + g) * WLD + kt * 8 + tq;
                b[nt][0] = wp[0];
                b[nt][1] = wp[4];
            }
            const uint32_t abase = (kt < 8)
                ? (hb0 + wroff + (uint32_t)(kt * 32))                 // h0' in write buf
                : (hb0 + rdoff + 256u + (uint32_t)((kt - 8) * 32));   // h1 in read buf
#pragma unroll
            for (int mt = 0; mt < 2; ++mt) {
                uint32_t a[4];
                ldmA(a, abase + (uint32_t)(mt * 16 * HLD * 4));
#pragma unroll
                for (int nt = 0; nt < 4; ++nt)
                    mma16(acc[mt][nt], a, b[nt]);
            }
        }

        // ---- epilogue1: h1' = tanh(D + b1) -> h1[wr]; dense partials ----
#pragma unroll
        for (int mt = 0; mt < 2; ++mt)
#pragma unroll
            for (int hh = 0; hh < 2; ++hh) {
                const int row = mt * 16 + g + hh * 8;
                float q0 = 0.f, q1 = 0.f;
#pragma unroll
                for (int nt = 0; nt < 4; ++nt) {
                    const int jc = 32 * w + nt * 8 + 2 * tq;
                    float v0 = acc[mt][nt][hh * 2]     + sB1v[jc];
                    float v1 = acc[mt][nt][hh * 2 + 1] + sB1v[jc + 1];
                    float t0 = tanh_fast(v0), t1 = tanh_fast(v1);
                    q0 = fmaf(t0, sWd[jc], fmaf(t1, sWd[jc + 1], q0));
                    q1 = fmaf(t0, sWd[128 + jc], fmaf(t1, sWd[128 + jc + 1], q1));
                    hcwm[row * HLD + 64 + 16 * w + nt * 4 + tq] = pk_bf(t0, t1);
                }
                q0 += __shfl_xor_sync(0xffffffffu, q0, 1);
                q0 += __shfl_xor_sync(0xffffffffu, q0, 2);
                q1 += __shfl_xor_sync(0xffffffffu, q1, 1);
                q1 += __shfl_xor_sync(0xffffffffu, q1, 2);
                if (tq == 0) {
                    sPart[w * 64 + row]      = q0;
                    sPart[w * 64 + 32 + row] = q1;
                }
            }

        // ---- dense tail: only warp 0 blocks; warps 1-3 run ahead into L0(t+1) ----
        if (w == 0) {
            BAR_SYNC(2);        // wait for all sPart writes
            float L0 = bd0, L1 = bd1;
#pragma unroll
            for (int ww = 0; ww < 4; ++ww) {
                L0 += sPart[ww * 64 + lane];
                L1 += sPart[ww * 64 + 32 + lane];
            }
            float m = fmaxf(L0, L1);
            float lse = m + __logf(__expf(L0 - m) + __expf(L1 - m));
            int bit = (s1 > 0.5f) ? 1 : 0;
            lp += (bit ? L1 : L0) - lse;
            sBit[lane] = bit;
        } else {
            BAR_ARRIVE(2);
        }
    }

    if (tid < BC) out[gRow] = lp;
}

extern "C" void kernel_launch(void* const* d_in, const int* in_sizes, int n_in,
                              void* d_out, int out_size) {
    (void)in_sizes; (void)n_in; (void)out_size;
    cudaFuncSetAttribute(rnn_bf16k_kernel,
                         cudaFuncAttributeMaxDynamicSharedMemorySize, SMEM_BYTES);
    rnn_bf16k_kernel<<<BATCH / BC, NT, SMEM_BYTES>>>(
        (const float*)d_in[0],
        (const float*)d_in[1], (const float*)d_in[2],
        (const float*)d_in[3], (const float*)d_in[4],
        (const float*)d_in[5], (const float*)d_in[6],
        (const float*)d_in[7], (const float*)d_in[8],
        (const float*)d_in[9], (const float*)d_in[10],
        (float*)d_out);
}